// round 15
// baseline (speedup 1.0000x reference)
#include <cuda_runtime.h>
#include <cuda_bf16.h>
#include <math.h>
#include <stdint.h>

// Problem constants
#define BB   4
#define HH   16
#define LL   2048
#define DD   1024
#define HD   64
#define CH   128
#define NC   16

// ---------------- scratch (device globals) ----------------
__device__ float g_S[BB*HH*NC*HD*HD];        // raw per-chunk states (fp32)
__device__ float g_z[BB*HH*NC*HD];
__device__ __nv_bfloat16 g_Sph[BB*HH*NC*HD*HD];  // exclusive-prefix S, split
__device__ __nv_bfloat16 g_Spl[BB*HH*NC*HD*HD];
__device__ __nv_bfloat16 g_xh[BB*LL*DD];
__device__ __nv_bfloat16 g_xl[BB*LL*DD];
__device__ __nv_bfloat16 g_wh[4*DD*DD];
__device__ __nv_bfloat16 g_wl[4*DD*DD];
__device__ __nv_bfloat16 g_qh[BB*HH*LL*HD];
__device__ __nv_bfloat16 g_ql[BB*HH*LL*HD];
__device__ __nv_bfloat16 g_kh[BB*HH*LL*HD];
__device__ __nv_bfloat16 g_kl[BB*HH*LL*HD];
__device__ __nv_bfloat16 g_vh[BB*HH*LL*HD];
__device__ __nv_bfloat16 g_vl[BB*HH*LL*HD];
__device__ __nv_bfloat16 g_oh[BB*LL*DD];
__device__ __nv_bfloat16 g_ol[BB*LL*DD];

// ---------------- PTX helpers ----------------
__device__ __forceinline__ uint32_t s2u(const void* p) {
    uint32_t a;
    asm("{ .reg .u64 t; cvta.to.shared.u64 t, %1; cvt.u32.u64 %0, t; }" : "=r"(a) : "l"(p));
    return a;
}
__device__ __forceinline__ void cp16(uint32_t s, const void* g) {
    asm volatile("cp.async.cg.shared.global [%0], [%1], 16;" :: "r"(s), "l"(g) : "memory");
}
__device__ __forceinline__ void ldm_x4(uint32_t* r, uint32_t addr) {
    asm volatile("ldmatrix.sync.aligned.m8n8.x4.shared.b16 {%0,%1,%2,%3}, [%4];"
        : "=r"(r[0]), "=r"(r[1]), "=r"(r[2]), "=r"(r[3]) : "r"(addr));
}
__device__ __forceinline__ void ldm_x4_t(uint32_t* r, uint32_t addr) {
    asm volatile("ldmatrix.sync.aligned.m8n8.x4.trans.shared.b16 {%0,%1,%2,%3}, [%4];"
        : "=r"(r[0]), "=r"(r[1]), "=r"(r[2]), "=r"(r[3]) : "r"(addr));
}
__device__ __forceinline__ void mma16816(float* d, const uint32_t* a, const uint32_t* b) {
    asm volatile("mma.sync.aligned.m16n8k16.row.col.f32.bf16.bf16.f32 "
        "{%0,%1,%2,%3}, {%4,%5,%6,%7}, {%8,%9}, {%0,%1,%2,%3};"
        : "+f"(d[0]), "+f"(d[1]), "+f"(d[2]), "+f"(d[3])
        : "r"(a[0]), "r"(a[1]), "r"(a[2]), "r"(a[3]), "r"(b[0]), "r"(b[1]));
}
__device__ __forceinline__ uint32_t pk2(float lo, float hi) {
    uint32_t r;
    asm("cvt.rn.bf16x2.f32 %0, %1, %2;" : "=r"(r) : "f"(hi), "f"(lo));
    return r;
}
__device__ __forceinline__ float bfh(float x) {
    return __bfloat162float(__float2bfloat16(x));
}
// 128B-row XOR swizzle
__device__ __forceinline__ uint32_t isw(int row, int colb) {
    return (uint32_t)(row * 128 + ((((colb >> 4) ^ (row & 7)) << 4) | (colb & 15)));
}

// ---------------- split fp32 -> bf16 hi + bf16 lo (x + all 4 weights) ----
__global__ __launch_bounds__(256) void split_all_kernel(
    const float* __restrict__ x,
    const float* __restrict__ Wq, const float* __restrict__ Wk,
    const float* __restrict__ Wv, const float* __restrict__ Wo)
{
    const int XN = BB * LL * DD;
    long long i = ((long long)blockIdx.x * 256 + threadIdx.x) * 4;
    const float* src;
    __nv_bfloat16 *dh, *dl;
    long long off;
    if (i < XN) {
        src = x; dh = g_xh; dl = g_xl; off = i;
    } else {
        long long j = i - XN;
        int w = (int)(j >> 20);
        off = j & ((1 << 20) - 1);
        src = (w == 0) ? Wq : (w == 1) ? Wk : (w == 2) ? Wv : Wo;
        dh = g_wh + ((long long)w << 20);
        dl = g_wl + ((long long)w << 20);
    }
    float4 v = *reinterpret_cast<const float4*>(src + off);
    __nv_bfloat16 h0 = __float2bfloat16(v.x), h1 = __float2bfloat16(v.y);
    __nv_bfloat16 h2 = __float2bfloat16(v.z), h3 = __float2bfloat16(v.w);
    __nv_bfloat16 l0 = __float2bfloat16(v.x - __bfloat162float(h0));
    __nv_bfloat16 l1 = __float2bfloat16(v.y - __bfloat162float(h1));
    __nv_bfloat16 l2 = __float2bfloat16(v.z - __bfloat162float(h2));
    __nv_bfloat16 l3 = __float2bfloat16(v.w - __bfloat162float(h3));
    __nv_bfloat162 ph0; ph0.x = h0; ph0.y = h1;
    __nv_bfloat162 ph1; ph1.x = h2; ph1.y = h3;
    __nv_bfloat162 pl0; pl0.x = l0; pl0.y = l1;
    __nv_bfloat162 pl1; pl1.x = l2; pl1.y = l3;
    *reinterpret_cast<__nv_bfloat162*>(dh + off)     = ph0;
    *reinterpret_cast<__nv_bfloat162*>(dh + off + 2) = ph1;
    *reinterpret_cast<__nv_bfloat162*>(dl + off)     = pl0;
    *reinterpret_cast<__nv_bfloat162*>(dl + off + 2) = pl1;
}

// =======================================================================
// HMMA split-bf16 GEMM. 256 thr, 2 CTAs/SM. Term-major MMA ordering:
// accumulator reuse distance 4 (was 1) to break RAW issue chains.
// Per-element term order unchanged (hh, hl, lh) -> bit-identical.
// =======================================================================
#define G_LDS 80
#define G_MAT (128 * G_LDS)
#define G_STG (4 * G_MAT)
#define GEMM_SMEM (2 * G_STG)      // 81920

__global__ __launch_bounds__(256, 2) void gemm_tc(
    const __nv_bfloat16* __restrict__ Ah0, const __nv_bfloat16* __restrict__ Al0,
    const float* __restrict__ bq, const float* __restrict__ bk, const float* __restrict__ bv,
    float* __restrict__ outp, int qkv_mode)
{
    extern __shared__ char smem[];
    const uint32_t sb = s2u(smem);
    const int tid = threadIdx.x;
    const int wid = tid >> 5, lane = tid & 31;
    const int wm = wid & 1, wn = wid >> 1;

    const __nv_bfloat16 *Ah, *Al, *Bh, *Bl;
    const float* bias;
    __nv_bfloat16 *ohp = nullptr, *olp = nullptr;
    int n0, do_silu;
    if (qkv_mode) {
        int w = blockIdx.x >> 3;
        Bh = g_wh + (size_t)w * (DD * DD);
        Bl = g_wl + (size_t)w * (DD * DD);
        bias = (w == 0) ? bq : (w == 1) ? bk : bv;
        ohp = (w == 0) ? g_qh : (w == 1) ? g_kh : g_vh;
        olp = (w == 0) ? g_ql : (w == 1) ? g_kl : g_vl;
        do_silu = (w < 2);
        n0 = (blockIdx.x & 7) * 128;
        Ah = Ah0; Al = Al0;
    } else {
        Bh = g_wh + 3 * (size_t)(DD * DD);
        Bl = g_wl + 3 * (size_t)(DD * DD);
        bias = bq; do_silu = 0;
        n0 = blockIdx.x * 128;
        Ah = g_oh; Al = g_ol;
    }
    const int m0 = blockIdx.y * 128;

    float acc[4][4][4];
#pragma unroll
    for (int a = 0; a < 4; a++)
#pragma unroll
        for (int b = 0; b < 4; b++)
#pragma unroll
            for (int c = 0; c < 4; c++) acc[a][b][c] = 0.f;

    auto load_chunk = [&](int cc) {
        const int kc = cc * 32;
        const uint32_t st = sb + (uint32_t)(cc & 1) * G_STG;
#pragma unroll
        for (int i = 0; i < 2; i++) {
            int idx = tid + i * 256;
            int r = idx >> 2, g = idx & 3;
            uint32_t so = (uint32_t)(r * G_LDS + g * 16);
            size_t ea = (size_t)(m0 + r) * DD + kc + g * 8;
            size_t eb = (size_t)(n0 + r) * DD + kc + g * 8;
            cp16(st + 0 * G_MAT + so, Ah + ea);
            cp16(st + 1 * G_MAT + so, Al + ea);
            cp16(st + 2 * G_MAT + so, Bh + eb);
            cp16(st + 3 * G_MAT + so, Bl + eb);
        }
        asm volatile("cp.async.commit_group;" ::: "memory");
    };

    load_chunk(0);

    const int arow = wm * 64 + (lane & 15);
    const int acol = (lane >> 4) * 8;
    const int brow = wn * 32 + ((lane >> 4) << 3) + (lane & 7);
    const int bcol = ((lane >> 3) & 1) * 8;

    const int NK = 1024 / 32;
    for (int c = 0; c < NK; c++) {
        asm volatile("cp.async.wait_group 0;" ::: "memory");
        __syncthreads();
        if (c + 1 < NK) load_chunk(c + 1);

        const uint32_t st  = sb + (uint32_t)(c & 1) * G_STG;
        const uint32_t aAh = st, aAl = st + G_MAT, aBh = st + 2 * G_MAT, aBl = st + 3 * G_MAT;

#pragma unroll
        for (int h = 0; h < 2; h++) {
            uint32_t bhf[2][4], blf[2][4];
#pragma unroll
            for (int p = 0; p < 2; p++) {
                uint32_t off = (uint32_t)((brow + p * 16) * G_LDS + (bcol + h * 16) * 2);
                ldm_x4(bhf[p], aBh + off);
                ldm_x4(blf[p], aBl + off);
            }
#pragma unroll
            for (int mt = 0; mt < 4; mt++) {
                uint32_t ah[4], al[4];
                uint32_t off = (uint32_t)((arow + mt * 16) * G_LDS + (acol + h * 16) * 2);
                ldm_x4(ah, aAh + off);
                ldm_x4(al, aAl + off);
                // term-major: reuse distance 4 per accumulator
#pragma unroll
                for (int nt = 0; nt < 4; nt++)
                    mma16816(acc[mt][nt], ah, &bhf[nt >> 1][(nt & 1) * 2]);
#pragma unroll
                for (int nt = 0; nt < 4; nt++)
                    mma16816(acc[mt][nt], ah, &blf[nt >> 1][(nt & 1) * 2]);
#pragma unroll
                for (int nt = 0; nt < 4; nt++)
                    mma16816(acc[mt][nt], al, &bhf[nt >> 1][(nt & 1) * 2]);
            }
        }
    }

    float bv2[4][2];
#pragma unroll
    for (int nt = 0; nt < 4; nt++) {
        int col = n0 + wn * 32 + nt * 8 + 2 * (lane & 3);
        bv2[nt][0] = bias[col];
        bv2[nt][1] = bias[col + 1];
    }
#pragma unroll
    for (int mt = 0; mt < 4; mt++) {
#pragma unroll
        for (int half = 0; half < 2; half++) {
            int m = m0 + wm * 64 + mt * 16 + (lane >> 2) + half * 8;
            int b = m >> 11, lpos = m & 2047;
#pragma unroll
            for (int nt = 0; nt < 4; nt++) {
                int col = n0 + wn * 32 + nt * 8 + 2 * (lane & 3);
                float v0 = acc[mt][nt][half * 2 + 0] + bv2[nt][0];
                float v1 = acc[mt][nt][half * 2 + 1] + bv2[nt][1];
                if (do_silu) {
                    v0 = v0 / (1.f + expf(-v0));
                    v1 = v1 / (1.f + expf(-v1));
                }
                if (qkv_mode) {
                    int hidx = col >> 6, i2 = col & 63;
                    size_t po = ((size_t)((b << 4) | hidx) * LL + lpos) * HD + i2;
                    *reinterpret_cast<uint32_t*>(ohp + po) = pk2(v0, v1);
                    *reinterpret_cast<uint32_t*>(olp + po) =
                        pk2(v0 - bfh(v0), v1 - bfh(v1));
                } else {
                    *reinterpret_cast<float2*>(outp + (size_t)m * DD + col) =
                        make_float2(v0, v1);
                }
            }
        }
    }
}

// =======================================================================
// Per-chunk state on tensor cores (term-major MMA ordering)
// =======================================================================
#define CS_KH 0
#define CS_KL 16384
#define CS_VH 32768
#define CS_VL 49152
#define CS_SMEM 65536

__global__ __launch_bounds__(256, 3) void chunk_state_kernel()
{
    extern __shared__ char smc[];
    const uint32_t sb = s2u(smc);
    const int cid = blockIdx.x;
    const size_t base = (size_t)(cid >> 4) * LL * HD + (size_t)(cid & 15) * CH * HD;
    const int tid = threadIdx.x, wid = tid >> 5, lane = tid & 31;
    const int wm = wid & 3, wn = wid >> 2;

#pragma unroll
    for (int i = 0; i < 4; i++) {
        int idx = tid + i * 256;
        int r = idx >> 3, g = idx & 7;
        uint32_t so = (uint32_t)(r * 128 + ((g ^ (r & 7)) << 4));
        size_t src = base + (size_t)r * HD + g * 8;
        cp16(sb + CS_KH + so, g_kh + src);
        cp16(sb + CS_KL + so, g_kl + src);
        cp16(sb + CS_VH + so, g_vh + src);
        cp16(sb + CS_VL + so, g_vl + src);
    }
    asm volatile("cp.async.commit_group;" ::: "memory");
    asm volatile("cp.async.wait_group 0;" ::: "memory");
    __syncthreads();

    const int kra = (lane & 7) | ((lane >> 4) << 3);
    const int dca = ((lane >> 3) & 1) * 8;
    const int tkr = (lane & 7) | (((lane >> 3) & 1) << 3);
    const int tnc = (lane >> 4) << 3;

    float acc[4][4];
#pragma unroll
    for (int a = 0; a < 4; a++)
#pragma unroll
        for (int b = 0; b < 4; b++) acc[a][b] = 0.f;

#pragma unroll
    for (int g = 0; g < 8; g++) {
        uint32_t kah[4], kal[4];
        uint32_t offA = isw(g * 16 + kra, (wm * 16 + dca) * 2);
        ldm_x4_t(kah, sb + CS_KH + offA);
        ldm_x4_t(kal, sb + CS_KL + offA);
        uint32_t vbh[2][4], vbl[2][4];
#pragma unroll
        for (int p = 0; p < 2; p++) {
            uint32_t offB = isw(g * 16 + tkr, (wn * 32 + p * 16 + tnc) * 2);
            ldm_x4_t(vbh[p], sb + CS_VH + offB);
            ldm_x4_t(vbl[p], sb + CS_VL + offB);
        }
        // term-major
#pragma unroll
        for (int nt = 0; nt < 4; nt++)
            mma16816(acc[nt], kah, &vbh[nt >> 1][(nt & 1) * 2]);
#pragma unroll
        for (int nt = 0; nt < 4; nt++)
            mma16816(acc[nt], kah, &vbl[nt >> 1][(nt & 1) * 2]);
#pragma unroll
        for (int nt = 0; nt < 4; nt++)
            mma16816(acc[nt], kal, &vbh[nt >> 1][(nt & 1) * 2]);
    }

    float* Sp = g_S + (size_t)cid * 4096;
    const int r = lane >> 2, c2 = 2 * (lane & 3);
#pragma unroll
    for (int nt = 0; nt < 4; nt++) {
        int e = wn * 32 + nt * 8 + c2;
        int d0 = wm * 16 + r;
        Sp[d0 * 64 + e]           = acc[nt][0];
        Sp[d0 * 64 + e + 1]       = acc[nt][1];
        Sp[(d0 + 8) * 64 + e]     = acc[nt][2];
        Sp[(d0 + 8) * 64 + e + 1] = acc[nt][3];
    }

    if (tid < 64) {
        float s = 0.f;
        int d2 = tid * 2;
#pragma unroll 8
        for (int t = 0; t < 128; t++) {
            uint32_t off = isw(t, d2);
            s += __bfloat162float(*(__nv_bfloat16*)(smc + CS_KH + off)) +
                 __bfloat162float(*(__nv_bfloat16*)(smc + CS_KL + off));
        }
        g_z[(size_t)cid * 64 + tid] = s;
    }
}

// =======================================================================
// Parallel exclusive prefix; emits split-bf16 S directly
// =======================================================================
__global__ __launch_bounds__(256) void prefix2_kernel()
{
    const int PER = 4096 + 64;
    int idx = blockIdx.x * 256 + threadIdx.x;
    if (idx >= 64 * PER) return;
    int bh = idx / PER, rme = idx - bh * PER;
    if (rme < 4096) {
        float run = 0.f;
        size_t p = (size_t)bh * NC * 4096 + rme;
#pragma unroll
        for (int n = 0; n < NC; n++) {
            float t = g_S[p];
            g_Sph[p] = __float2bfloat16(run);
            g_Spl[p] = __float2bfloat16(run - bfh(run));
            run += t; p += 4096;
        }
    } else {
        int e = rme - 4096;
        float run = 0.f;
        size_t p = (size_t)bh * NC * 64 + e;
#pragma unroll
        for (int n = 0; n < NC; n++) {
            float t = g_z[p]; g_z[p] = run; run += t; p += 64;
        }
    }
}

// =======================================================================
// Intra-chunk attention (2 CTAs/SM, causal-skip, term-major MMA)
// =======================================================================
#define OFF_QH 0
#define OFF_QL 16384
#define OFF_KH 32768
#define OFF_KL 49152
#define OFF_VH 65536
#define OFF_VL 81920
#define OFF_SH 98304
#define OFF_SL 106496
#define OFF_Z  114688
#define OFF_DEN 114944
#define OFF_NUM OFF_KH
#define INTRA2_SMEM 115456

__global__ __launch_bounds__(256, 2) void intra2_kernel()
{
    extern __shared__ char smc[];
    float* numb = (float*)(smc + OFF_NUM);
    float* zs   = (float*)(smc + OFF_Z);
    float* den  = (float*)(smc + OFF_DEN);
    const uint32_t sb = s2u(smc);

    const int cid = blockIdx.x;
    const int bh = cid >> 4, nch = cid & 15;
    const size_t base = ((size_t)bh * LL + (size_t)nch * CH) * HD;
    const int tid = threadIdx.x, wid = tid >> 5, lane = tid & 31;
    const int wm = wid & 3, wn = wid >> 2;

    const uint32_t sQH = sb + OFF_QH, sQL = sb + OFF_QL;
    const uint32_t sKH = sb + OFF_KH, sKL = sb + OFF_KL;
    const uint32_t sVH = sb + OFF_VH, sVL = sb + OFF_VL;
    const uint32_t sSH = sb + OFF_SH, sSL = sb + OFF_SL;

#pragma unroll
    for (int i = 0; i < 4; i++) {
        int idx = tid + i * 256;
        int r = idx >> 3, g = idx & 7;
        uint32_t so = (uint32_t)(r * 128 + ((g ^ (r & 7)) << 4));
        size_t src = base + (size_t)r * HD + g * 8;
        cp16(sQH + so, g_qh + src);
        cp16(sQL + so, g_ql + src);
        cp16(sKH + so, g_kh + src);
        cp16(sKL + so, g_kl + src);
        cp16(sVH + so, g_vh + src);
        cp16(sVL + so, g_vl + src);
    }
#pragma unroll
    for (int i = 0; i < 2; i++) {
        int idx = tid + i * 256;
        int d = idx >> 3, g = idx & 7;
        uint32_t so = (uint32_t)(d * 128 + ((g ^ (d & 7)) << 4));
        size_t src = (size_t)cid * 4096 + (size_t)d * 64 + g * 8;
        cp16(sSH + so, g_Sph + src);
        cp16(sSL + so, g_Spl + src);
    }
    asm volatile("cp.async.commit_group;" ::: "memory");

    if (tid < 64) zs[tid] = g_z[(size_t)cid * 64 + tid];
    if (tid < 128) den[tid] = 0.f;
    asm volatile("cp.async.wait_group 0;" ::: "memory");
    __syncthreads();

    const int r = lane >> 2, c2 = 2 * (lane & 3);
    const int arow = wm * 32 + (lane & 15);
    const int acol = (lane >> 4) * 8;
    const int brow = ((lane >> 4) << 3) + (lane & 7);
    const int bcol = ((lane >> 3) & 1) * 8;
    const int tkr = (lane & 7) | (((lane >> 3) & 1) << 3);
    const int tnc = (lane >> 4) << 3;
    const int rmax = wm * 32 + 31;

    // ---- phase 1: scores = q k^T (causal-skip, term-major) ----
    float acc[2][8][4];
#pragma unroll
    for (int a = 0; a < 2; a++)
#pragma unroll
        for (int b = 0; b < 8; b++)
#pragma unroll
            for (int c = 0; c < 4; c++) acc[a][b][c] = 0.f;

    if (wn * 64 <= rmax) {
#pragma unroll
        for (int g = 0; g < 4; g++) {
            uint32_t qaf[2][4], qbf[2][4];
#pragma unroll
            for (int mt = 0; mt < 2; mt++) {
                uint32_t off = isw(arow + mt * 16, (acol + g * 16) * 2);
                ldm_x4(qaf[mt], sQH + off);
                ldm_x4(qbf[mt], sQL + off);
            }
            uint32_t kaf[4][4], kbf2[4][4];
#pragma unroll
            for (int p = 0; p < 4; p++) {
                if (wn * 64 + p * 16 <= rmax) {
                    uint32_t off = isw(wn * 64 + brow + p * 16, (bcol + g * 16) * 2);
                    ldm_x4(kaf[p], sKH + off);
                    ldm_x4(kbf2[p], sKL + off);
                }
            }
#pragma unroll
            for (int mt = 0; mt < 2; mt++) {
#pragma unroll
                for (int nt = 0; nt < 8; nt++)
                    if (wn * 64 + nt * 8 <= wm * 32 + mt * 16 + 15)
                        mma16816(acc[mt][nt], qaf[mt], &kaf[nt >> 1][(nt & 1) * 2]);
#pragma unroll
                for (int nt = 0; nt < 8; nt++)
                    if (wn * 64 + nt * 8 <= wm * 32 + mt * 16 + 15)
                        mma16816(acc[mt][nt], qaf[mt], &kbf2[nt >> 1][(nt & 1) * 2]);
#pragma unroll
                for (int nt = 0; nt < 8; nt++)
                    if (wn * 64 + nt * 8 <= wm * 32 + mt * 16 + 15)
                        mma16816(acc[mt][nt], qbf[mt], &kaf[nt >> 1][(nt & 1) * 2]);
            }
        }
    }

    // ---- mask + rowsum (den) + split scores ----
    uint32_t shf[2][4][4], slf[2][4][4];
#pragma unroll
    for (int mt = 0; mt < 2; mt++) {
        float rs0 = 0.f, rs1 = 0.f;
        int i0 = wm * 32 + mt * 16 + r, i1 = i0 + 8;
#pragma unroll
        for (int nt = 0; nt < 8; nt++) {
            int j0 = wn * 64 + nt * 8 + c2;
            float s00 = (j0     <= i0) ? acc[mt][nt][0] : 0.f;
            float s01 = (j0 + 1 <= i0) ? acc[mt][nt][1] : 0.f;
            float s10 = (j0     <= i1) ? acc[mt][nt][2] : 0.f;
            float s11 = (j0 + 1 <= i1) ? acc[mt][nt][3] : 0.f;
            rs0 += s00 + s01;
            rs1 += s10 + s11;
            int g = nt >> 1, hh = (nt & 1) * 2;
            shf[mt][g][hh]     = pk2(s00, s01);
            shf[mt][g][hh + 1] = pk2(s10, s11);
            slf[mt][g][hh]     = pk2(s00 - bfh(s00), s01 - bfh(s01));
            slf[mt][g][hh + 1] = pk2(s10 - bfh(s10), s11 - bfh(s11));
        }
        rs0 += __shfl_xor_sync(0xffffffffu, rs0, 1);
        rs0 += __shfl_xor_sync(0xffffffffu, rs0, 2);
        rs1 += __shfl_xor_sync(0xffffffffu, rs1, 1);
        rs1 += __shfl_xor_sync(0xffffffffu, rs1, 2);
        if ((lane & 3) == 0 && wn * 64 <= rmax) {
            atomicAdd(&den[i0], rs0);
            atomicAdd(&den[i1], rs1);
        }
    }

    // ---- den += q . z ----
    if (tid < 128) {
        float s = 0.f;
        int tmask = tid & 7;
#pragma unroll 8
        for (int d = 0; d < 64; d++) {
            uint32_t off = (uint32_t)(tid * 128 + ((((d >> 3) ^ tmask) << 4) | ((d & 7) * 2)));
            float qv = __bfloat162float(*(__nv_bfloat16*)(smc + OFF_QH + off)) +
                       __bfloat162float(*(__nv_bfloat16*)(smc + OFF_QL + off));
            s += qv * zs[d];
        }
        atomicAdd(&den[tid], s);
    }

    // ---- phase 2 in two output-column halves (term-major) ----
    const int bidx = bh >> 4, hd = bh & 15;
#pragma unroll 1
    for (int eh = 0; eh < 2; eh++) {
        float acc2[2][4][4];
#pragma unroll
        for (int a = 0; a < 2; a++)
#pragma unroll
            for (int b = 0; b < 4; b++)
#pragma unroll
                for (int c = 0; c < 4; c++) acc2[a][b][c] = 0.f;

#pragma unroll
        for (int g = 0; g < 4; g++) {
            if (wn * 64 + g * 16 <= rmax) {
                uint32_t vaf[2][4], vbf2[2][4];
#pragma unroll
                for (int p2 = 0; p2 < 2; p2++) {
                    int pg = eh * 2 + p2;
                    uint32_t off = isw(wn * 64 + g * 16 + tkr, (pg * 16 + tnc) * 2);
                    ldm_x4_t(vaf[p2], sVH + off);
                    ldm_x4_t(vbf2[p2], sVL + off);
                }
#pragma unroll
                for (int mt = 0; mt < 2; mt++) {
                    if (wn * 64 + g * 16 <= wm * 32 + mt * 16 + 15) {
#pragma unroll
                        for (int nt = 0; nt < 4; nt++)
                            mma16816(acc2[mt][nt], shf[mt][g], &vaf[nt >> 1][(nt & 1) * 2]);
#pragma unroll
                        for (int nt = 0; nt < 4; nt++)
                            mma16816(acc2[mt][nt], shf[mt][g], &vbf2[nt >> 1][(nt & 1) * 2]);
#pragma unroll
                        for (int nt = 0; nt < 4; nt++)
                            mma16816(acc2[mt][nt], slf[mt][g], &vaf[nt >> 1][(nt & 1) * 2]);
                    }
                }
            }
        }
#pragma unroll
        for (int g2 = 0; g2 < 2; g2++) {
            int gd = wn * 2 + g2;
            uint32_t qaf[2][4], qbf[2][4];
#pragma unroll
            for (int mt = 0; mt < 2; mt++) {
                uint32_t off = isw(arow + mt * 16, (acol + gd * 16) * 2);
                ldm_x4(qaf[mt], sQH + off);
                ldm_x4(qbf[mt], sQL + off);
            }
            uint32_t Saf[2][4], Sbf2[2][4];
#pragma unroll
            for (int p2 = 0; p2 < 2; p2++) {
                int pg = eh * 2 + p2;
                uint32_t off = isw(gd * 16 + tkr, (pg * 16 + tnc) * 2);
                ldm_x4_t(Saf[p2], sSH + off);
                ldm_x4_t(Sbf2[p2], sSL + off);
            }
#pragma unroll
            for (int mt = 0; mt < 2; mt++) {
#pragma unroll
                for (int nt = 0; nt < 4; nt++)
                    mma16816(acc2[mt][nt], qaf[mt], &Saf[nt >> 1][(nt & 1) * 2]);
#pragma unroll
                for (int nt = 0; nt < 4; nt++)
                    mma16816(acc2[mt][nt], qaf[mt], &Sbf2[nt >> 1][(nt & 1) * 2]);
#pragma unroll
                for (int nt = 0; nt < 4; nt++)
                    mma16816(acc2[mt][nt], qbf[mt], &Saf[nt >> 1][(nt & 1) * 2]);
            }
        }

        __syncthreads();
        if (wn == 0) {
#pragma unroll
            for (int mt = 0; mt < 2; mt++) {
                int i0 = wm * 32 + mt * 16 + r;
#pragma unroll
                for (int nt = 0; nt < 4; nt++) {
                    int cl = nt * 8 + c2;
                    numb[i0 * 32 + cl]           = acc2[mt][nt][0];
                    numb[i0 * 32 + cl + 1]       = acc2[mt][nt][1];
                    numb[(i0 + 8) * 32 + cl]     = acc2[mt][nt][2];
                    numb[(i0 + 8) * 32 + cl + 1] = acc2[mt][nt][3];
                }
            }
        }
        __syncthreads();
        if (wn == 1) {
#pragma unroll
            for (int mt = 0; mt < 2; mt++) {
                int i0 = wm * 32 + mt * 16 + r;
                float dr0 = 1.f / fmaxf(den[i0], 1e-3f);
                float dr1 = 1.f / fmaxf(den[i0 + 8], 1e-3f);
                int l0 = nch * CH + i0;
                size_t ob0 = ((size_t)bidx * LL + l0) * DD + hd * 64 + eh * 32;
                size_t ob1 = ((size_t)bidx * LL + l0 + 8) * DD + hd * 64 + eh * 32;
#pragma unroll
                for (int nt = 0; nt < 4; nt++) {
                    int cl = nt * 8 + c2;
                    float o00 = (acc2[mt][nt][0] + numb[i0 * 32 + cl])           * dr0;
                    float o01 = (acc2[mt][nt][1] + numb[i0 * 32 + cl + 1])       * dr0;
                    float o10 = (acc2[mt][nt][2] + numb[(i0 + 8) * 32 + cl])     * dr1;
                    float o11 = (acc2[mt][nt][3] + numb[(i0 + 8) * 32 + cl + 1]) * dr1;
                    *reinterpret_cast<uint32_t*>(g_oh + ob0 + cl) = pk2(o00, o01);
                    *reinterpret_cast<uint32_t*>(g_oh + ob1 + cl) = pk2(o10, o11);
                    *reinterpret_cast<uint32_t*>(g_ol + ob0 + cl) =
                        pk2(o00 - bfh(o00), o01 - bfh(o01));
                    *reinterpret_cast<uint32_t*>(g_ol + ob1 + cl) =
                        pk2(o10 - bfh(o10), o11 - bfh(o11));
                }
            }
        }
        __syncthreads();
    }
}

// =======================================================================
extern "C" void kernel_launch(void* const* d_in, const int* in_sizes, int n_in,
                              void* d_out, int out_size)
{
    const float* x  = (const float*)d_in[0];
    const float* Wq = (const float*)d_in[1];
    const float* bq = (const float*)d_in[2];
    const float* Wk = (const float*)d_in[3];
    const float* bk = (const float*)d_in[4];
    const float* Wv = (const float*)d_in[5];
    const float* bv = (const float*)d_in[6];
    const float* Wo = (const float*)d_in[7];
    const float* bo = (const float*)d_in[8];
    float* out = (float*)d_out;

    cudaFuncSetAttribute(chunk_state_kernel, cudaFuncAttributeMaxDynamicSharedMemorySize, CS_SMEM);
    cudaFuncSetAttribute(intra2_kernel, cudaFuncAttributeMaxDynamicSharedMemorySize, INTRA2_SMEM);
    cudaFuncSetAttribute(gemm_tc, cudaFuncAttributeMaxDynamicSharedMemorySize, GEMM_SMEM);

    __nv_bfloat16 *xh, *xl;
    cudaGetSymbolAddress((void**)&xh, g_xh);
    cudaGetSymbolAddress((void**)&xl, g_xl);

    // 0) split fp32 inputs into bf16 hi/lo pairs
    split_all_kernel<<<(BB*LL*DD + 4*DD*DD) / 1024, 256>>>(x, Wq, Wk, Wv, Wo);

    // 1) fused QKV projection (2 CTAs/SM)
    gemm_tc<<<dim3(24, 64), 256, GEMM_SMEM>>>(xh, xl, bq, bk, bv, nullptr, 1);

    // 2) per-chunk kv state + k sums (tensor cores)
    chunk_state_kernel<<<BB * HH * NC, 256, CS_SMEM>>>();

    // 3) exclusive prefix; emits split-bf16 S
    prefix2_kernel<<<(64 * (4096 + 64) + 255) / 256, 256>>>();

    // 4) intra-chunk attention (2 CTAs/SM, causal-skip)
    intra2_kernel<<<BB * HH * NC, 256, INTRA2_SMEM>>>();

    // 5) output projection
    gemm_tc<<<dim3(8, 64), 256, GEMM_SMEM>>>(nullptr, nullptr, bo, bo, bo, out, 0);
}